// round 15
// baseline (speedup 1.0000x reference)
#include <cuda_runtime.h>
#include <cuda_bf16.h>
#include <cstdint>
#include <cstring>

#define N_NODES 50000
#define N_EDGES 500000
#define D 128

#define PITCHA 136   // HMMA activation plane pitch (bf16 elements)
#define PLANE   (128 * PITCHA)
#define PLANE64 (64 * PITCHA)

// ---------------- scratch (static device globals: allowed) ----------------
__device__ float g_mi[N_NODES * D];
__device__ float g_pa[N_NODES * D];   // h @ We1[0:128)   + be1
__device__ float g_pb[N_NODES * D];   // h @ We1[128:256)
// fragment-ordered weight image: 64 ktile-slots x 16 ntiles x 32 lanes x uint4
// 0-7 We1[0:128), 8-15 We1[128:256), 16-23 We2, 24-31 Wc1,
// 32-39 Wn1[0:128), 40-47 Wn1[128:256), 48-55 Wn2, 56-63 Wv1
__device__ uint4 g_bimg[64 * 16 * 32];

__device__ __forceinline__ float silu(float x) { return x / (1.0f + __expf(-x)); }

__device__ __forceinline__ uint32_t bf2_as_u32(__nv_bfloat162 v) {
    uint32_t u; memcpy(&u, &v, 4); return u;
}
__device__ __forceinline__ uint32_t smem_u32(const void* p) {
    uint32_t a;
    asm("{ .reg .u64 t; cvta.to.shared.u64 t, %1; cvt.u32.u64 %0, t; }" : "=r"(a) : "l"(p));
    return a;
}

__device__ __forceinline__ void mma_bf16(
    float* c, uint32_t a0, uint32_t a1, uint32_t a2, uint32_t a3,
    uint32_t b0, uint32_t b1)
{
    asm volatile(
        "mma.sync.aligned.m16n8k16.row.col.f32.bf16.bf16.f32 "
        "{%0,%1,%2,%3}, {%4,%5,%6,%7}, {%8,%9}, {%0,%1,%2,%3};"
        : "+f"(c[0]), "+f"(c[1]), "+f"(c[2]), "+f"(c[3])
        : "r"(a0), "r"(a1), "r"(a2), "r"(a3), "r"(b0), "r"(b1));
}

__device__ __forceinline__ void ldsm_x4(
    uint32_t& r0, uint32_t& r1, uint32_t& r2, uint32_t& r3, uint32_t addr)
{
    asm volatile("ldmatrix.sync.aligned.m8n8.x4.shared.b16 {%0,%1,%2,%3}, [%4];"
                 : "=r"(r0), "=r"(r1), "=r"(r2), "=r"(r3) : "r"(addr));
}

__device__ __forceinline__ void split_pair(
    float x, float y, __nv_bfloat162& hi, __nv_bfloat162& lo)
{
    hi = __floats2bfloat162_rn(x, y);
    lo = __floats2bfloat162_rn(x - __low2float(hi), y - __high2float(hi));
}

// packed f32 pair reduction (sm_90+ baseline): 8B-aligned dst required
__device__ __forceinline__ void red_add_v2(float* p, float a, float b) {
    asm volatile("red.global.add.v2.f32 [%0], {%1, %2};"
                 :: "l"(p), "f"(a), "f"(b) : "memory");
}

// ---------------------------------------------------------------------------
__global__ void zero_mi_kernel() {
    int i = blockIdx.x * blockDim.x + threadIdx.x;
    if (i < N_NODES * D / 4)
        reinterpret_cast<float4*>(g_mi)[i] = make_float4(0.f, 0.f, 0.f, 0.f);
}

// ---------------------------------------------------------------------------
__global__ void prep_bimg_kernel(
    const float* __restrict__ We1, const float* __restrict__ We2,
    const float* __restrict__ Wc1, const float* __restrict__ Wn1,
    const float* __restrict__ Wn2, const float* __restrict__ Wv1)
{
    int idx = blockIdx.x * 256 + threadIdx.x;
    if (idx >= 64 * 16 * 32) return;
    int lane = idx & 31;
    int nt = (idx >> 5) & 15;
    int s = idx >> 9;
    int col = nt * 8 + (lane >> 2);
    int kloc = 2 * (lane & 3);
    const float* W; int kr;
    if (s < 8)       { W = We1; kr = s * 16 + kloc; }
    else if (s < 16) { W = We1; kr = 128 + (s - 8) * 16 + kloc; }
    else if (s < 24) { W = We2; kr = (s - 16) * 16 + kloc; }
    else if (s < 32) { W = Wc1; kr = (s - 24) * 16 + kloc; }
    else if (s < 40) { W = Wn1; kr = (s - 32) * 16 + kloc; }
    else if (s < 48) { W = Wn1; kr = 128 + (s - 40) * 16 + kloc; }
    else if (s < 56) { W = Wn2; kr = (s - 48) * 16 + kloc; }
    else             { W = Wv1; kr = (s - 56) * 16 + kloc; }
    float f00 = W[kr * D + col];
    float f01 = W[(kr + 1) * D + col];
    float f10 = W[(kr + 8) * D + col];
    float f11 = W[(kr + 9) * D + col];
    __nv_bfloat162 h0, l0, h1, l1;
    split_pair(f00, f01, h0, l0);
    split_pair(f10, f11, h1, l1);
    uint4 v;
    v.x = bf2_as_u32(h0); v.y = bf2_as_u32(h1);
    v.z = bf2_as_u32(l0); v.w = bf2_as_u32(l1);
    g_bimg[idx] = v;
}

// ---------------------------------------------------------------------------
// 128-row software-pipelined warp-tile GEMM (3-pass hi/lo bf16) — pab/node_post
__device__ __forceinline__ void gemm_tile(
    float (&c)[4][4][4], uint32_t aHi_addr, int base,
    int cg, int rg, int lane)
{
    int lrow = lane & 15;
    int lcol = (lane >> 4) * 8;
    const uint4* bp = g_bimg + (base * 16 + cg * 4) * 32 + lane;
    uint4 b[4], bn[4];
    #pragma unroll
    for (int nt = 0; nt < 4; nt++) b[nt] = __ldg(bp + nt * 32);
    uint32_t abase = aHi_addr + (uint32_t)(((rg * 64 + lrow) * PITCHA + lcol) * 2);
    uint32_t ah[2][4], al[2][4];
    ldsm_x4(ah[0][0], ah[0][1], ah[0][2], ah[0][3], abase);
    ldsm_x4(al[0][0], al[0][1], al[0][2], al[0][3], abase + PLANE * 2);
    #pragma unroll
    for (int kt = 0; kt < 8; kt++) {
        if (kt < 7) {
            #pragma unroll
            for (int nt = 0; nt < 4; nt++) bn[nt] = __ldg(bp + 16 * 32 + nt * 32);
        }
        #pragma unroll
        for (int mt = 0; mt < 4; mt++) {
            int cur = mt & 1, nxt = 1 - cur;
            if (mt < 3) {
                uint32_t addr = abase + (uint32_t)((((mt + 1) * 16) * PITCHA + kt * 16) * 2);
                ldsm_x4(ah[nxt][0], ah[nxt][1], ah[nxt][2], ah[nxt][3], addr);
                ldsm_x4(al[nxt][0], al[nxt][1], al[nxt][2], al[nxt][3], addr + PLANE * 2);
            } else if (kt < 7) {
                uint32_t addr = abase + (uint32_t)(((kt + 1) * 16) * 2);
                ldsm_x4(ah[nxt][0], ah[nxt][1], ah[nxt][2], ah[nxt][3], addr);
                ldsm_x4(al[nxt][0], al[nxt][1], al[nxt][2], al[nxt][3], addr + PLANE * 2);
            }
            #pragma unroll
            for (int nt = 0; nt < 4; nt++) {
                mma_bf16(c[mt][nt], ah[cur][0], ah[cur][1], ah[cur][2], ah[cur][3], b[nt].x, b[nt].y);
                mma_bf16(c[mt][nt], ah[cur][0], ah[cur][1], ah[cur][2], ah[cur][3], b[nt].z, b[nt].w);
                mma_bf16(c[mt][nt], al[cur][0], al[cur][1], al[cur][2], al[cur][3], b[nt].x, b[nt].y);
            }
        }
        #pragma unroll
        for (int nt = 0; nt < 4; nt++) b[nt] = bn[nt];
        bp += 16 * 32;
    }
}

// 64-row warp-tile GEMM (32 accumulators) — edge kernel, occupancy-optimized
__device__ __forceinline__ void gemm_tile64(
    float (&c)[2][4][4], uint32_t aHi_addr, int base,
    int cg, int rg, int lane)
{
    int lrow = lane & 15;
    int lcol = (lane >> 4) * 8;
    const uint4* bp = g_bimg + (base * 16 + cg * 4) * 32 + lane;
    uint32_t abase = aHi_addr + (uint32_t)(((rg * 32 + lrow) * PITCHA + lcol) * 2);
    #pragma unroll
    for (int kt = 0; kt < 8; kt++) {
        uint4 b[4];
        #pragma unroll
        for (int nt = 0; nt < 4; nt++) b[nt] = __ldg(bp + nt * 32);
        #pragma unroll
        for (int mt = 0; mt < 2; mt++) {
            uint32_t addr = abase + (uint32_t)(((mt * 16) * PITCHA + kt * 16) * 2);
            uint32_t ah0, ah1, ah2, ah3, al0, al1, al2, al3;
            ldsm_x4(ah0, ah1, ah2, ah3, addr);
            ldsm_x4(al0, al1, al2, al3, addr + PLANE64 * 2);
            #pragma unroll
            for (int nt = 0; nt < 4; nt++) {
                mma_bf16(c[mt][nt], ah0, ah1, ah2, ah3, b[nt].x, b[nt].y);
                mma_bf16(c[mt][nt], ah0, ah1, ah2, ah3, b[nt].z, b[nt].w);
                mma_bf16(c[mt][nt], al0, al1, al2, al3, b[nt].x, b[nt].y);
            }
        }
        bp += 16 * 32;
    }
}

#define BIG_SMEM  75776   // pab / node_post (128-row planes)
#define EDGE_SMEM 37632   // edge (64-row planes)

// ---------------------------------------------------------------------------
// pab_kernel (verified R11-R13): P_A, P_B, vel weights + coord base
__global__ __launch_bounds__(256, 2) void pab_kernel(
    const float* __restrict__ h, const float* __restrict__ be1,
    const float* __restrict__ coord, const float* __restrict__ vel,
    const float* __restrict__ bv1, const float* __restrict__ Wv2,
    const float* __restrict__ bv2,
    float* __restrict__ coord_out)
{
    extern __shared__ __align__(16) char smem[];
    __nv_bfloat16* aHi = (__nv_bfloat16*)smem;
    __nv_bfloat16* aLo = aHi + PLANE;
    float* s_be1 = (float*)(smem + 69632);
    float* s_bv1 = s_be1 + 128;
    float* s_wv2 = s_bv1 + 128;
    float* s_wp  = (float*)smem;

    int t = threadIdx.x;
    int lane = t & 31, wid = t >> 5;
    int cg = wid & 3, rg = wid >> 2;
    int n0 = blockIdx.x * 128;
    uint32_t aHi_addr = smem_u32(aHi);

    if (t < 128) { s_be1[t] = be1[t]; s_bv1[t] = bv1[t]; s_wv2[t] = Wv2[t]; }

    // stage h rows (hi/lo), packed STS.128
    {
        int r = t >> 1;
        int node = n0 + r; if (node >= N_NODES) node = N_NODES - 1;
        int ch = (t & 1) * 64;
        const float* src = h + node * D + ch;
        uint4* ph = (uint4*)(aHi + r * PITCHA + ch);
        uint4* pl = (uint4*)(aLo + r * PITCHA + ch);
        #pragma unroll
        for (int jj = 0; jj < 8; jj++) {
            float4 v0 = *(const float4*)(src + 8 * jj);
            float4 v1 = *(const float4*)(src + 8 * jj + 4);
            __nv_bfloat162 ha, la, hb, lb, hc, lc, hd, ld;
            split_pair(v0.x, v0.y, ha, la);
            split_pair(v0.z, v0.w, hb, lb);
            split_pair(v1.x, v1.y, hc, lc);
            split_pair(v1.z, v1.w, hd, ld);
            uint4 HV, LV;
            HV.x = bf2_as_u32(ha); HV.y = bf2_as_u32(hb);
            HV.z = bf2_as_u32(hc); HV.w = bf2_as_u32(hd);
            LV.x = bf2_as_u32(la); LV.y = bf2_as_u32(lb);
            LV.z = bf2_as_u32(lc); LV.w = bf2_as_u32(ld);
            ph[jj] = HV;
            pl[jj] = LV;
        }
    }
    __syncthreads();

    float c[4][4][4];
    #pragma unroll
    for (int mt = 0; mt < 4; mt++)
        #pragma unroll
        for (int nt = 0; nt < 4; nt++)
            #pragma unroll
            for (int j = 0; j < 4; j++) c[mt][nt][j] = 0.f;

    int q = lane >> 2;
    int kq = 2 * (lane & 3);

    gemm_tile(c, aHi_addr, 0, cg, rg, lane);
    #pragma unroll
    for (int mt = 0; mt < 4; mt++) {
        int row0 = rg * 64 + mt * 16 + q;
        int row1 = row0 + 8;
        bool v0 = (n0 + row0) < N_NODES, v1 = (n0 + row1) < N_NODES;
        #pragma unroll
        for (int nt = 0; nt < 4; nt++) {
            int col = cg * 32 + nt * 8 + kq;
            float b0 = s_be1[col], b1 = s_be1[col + 1];
            if (v0) *(float2*)&g_pa[(n0 + row0) * D + col] =
                make_float2(c[mt][nt][0] + b0, c[mt][nt][1] + b1);
            if (v1) *(float2*)&g_pa[(n0 + row1) * D + col] =
                make_float2(c[mt][nt][2] + b0, c[mt][nt][3] + b1);
            c[mt][nt][0] = c[mt][nt][1] = c[mt][nt][2] = c[mt][nt][3] = 0.f;
        }
    }
    gemm_tile(c, aHi_addr, 8, cg, rg, lane);
    #pragma unroll
    for (int mt = 0; mt < 4; mt++) {
        int row0 = rg * 64 + mt * 16 + q;
        int row1 = row0 + 8;
        bool v0 = (n0 + row0) < N_NODES, v1 = (n0 + row1) < N_NODES;
        #pragma unroll
        for (int nt = 0; nt < 4; nt++) {
            int col = cg * 32 + nt * 8 + kq;
            if (v0) *(float2*)&g_pb[(n0 + row0) * D + col] =
                make_float2(c[mt][nt][0], c[mt][nt][1]);
            if (v1) *(float2*)&g_pb[(n0 + row1) * D + col] =
                make_float2(c[mt][nt][2], c[mt][nt][3]);
            c[mt][nt][0] = c[mt][nt][1] = c[mt][nt][2] = c[mt][nt][3] = 0.f;
        }
    }
    gemm_tile(c, aHi_addr, 56, cg, rg, lane);
    __syncthreads();
    #pragma unroll
    for (int mt = 0; mt < 4; mt++) {
        float p0 = 0.f, p1 = 0.f;
        #pragma unroll
        for (int nt = 0; nt < 4; nt++) {
            int col = cg * 32 + nt * 8 + kq;
            float b0 = s_bv1[col], b1 = s_bv1[col + 1];
            float w0 = s_wv2[col], w1 = s_wv2[col + 1];
            p0 = fmaf(silu(c[mt][nt][0] + b0), w0, p0);
            p0 = fmaf(silu(c[mt][nt][1] + b1), w1, p0);
            p1 = fmaf(silu(c[mt][nt][2] + b0), w0, p1);
            p1 = fmaf(silu(c[mt][nt][3] + b1), w1, p1);
        }
        p0 += __shfl_xor_sync(0xffffffffu, p0, 1);
        p0 += __shfl_xor_sync(0xffffffffu, p0, 2);
        p1 += __shfl_xor_sync(0xffffffffu, p1, 1);
        p1 += __shfl_xor_sync(0xffffffffu, p1, 2);
        if ((lane & 3) == 0) {
            int row0 = rg * 64 + mt * 16 + q;
            s_wp[row0 * 4 + cg]       = p0;
            s_wp[(row0 + 8) * 4 + cg] = p1;
        }
    }
    __syncthreads();
    if (t < 128 && (n0 + t) < N_NODES) {
        float vw = s_wp[t * 4] + s_wp[t * 4 + 1] + s_wp[t * 4 + 2] + s_wp[t * 4 + 3] + bv2[0];
        int n = n0 + t;
        #pragma unroll
        for (int i = 0; i < 3; i++)
            coord_out[n * 3 + i] = coord[n * 3 + i] + vel[n * 3 + i] * vw;
    }
}

// ---------------------------------------------------------------------------
// edge kernel: 64 edges/block, 32-acc warp tiles, 3 blocks/SM, packed stores
__global__ __launch_bounds__(256, 3) void edge_kernel(
    const float* __restrict__ coord,
    const int* __restrict__ ei,
    const float* __restrict__ be2,
    const float* __restrict__ bc1,
    const float* __restrict__ Wc2, const float* __restrict__ bc2,
    const float* __restrict__ We1,
    float* __restrict__ coord_out)
{
    extern __shared__ __align__(16) char smem[];
    __nv_bfloat16* aHi = (__nv_bfloat16*)smem;              // 17408 B
    __nv_bfloat16* aLo = aHi + PLANE64;                     // 17408 B
    float* s_be2  = (float*)(smem + 34816);
    float* s_bc1  = s_be2 + 128;
    float* s_wc2  = s_bc1 + 128;
    int*   s_r    = (int*)(smem + 36352);    // 64 ints
    float* s_diff = (float*)(smem + 36608);  // 64*3 floats
    float* s_wp   = (float*)smem;            // L3 partials alias plane

    int t = threadIdx.x;
    int lane = t & 31, wid = t >> 5;
    int cg = wid & 3, rg = wid >> 2;        // rg in {0,1}
    int e0 = blockIdx.x * 64;

    uint32_t aHi_addr = smem_u32(aHi);

    if (t < 128) { s_be2[t] = be2[t]; s_bc1[t] = bc1[t]; s_wc2[t] = Wc2[t]; }

    // ---- per-thread gather + act1 (packed STS.128 stores) ----
    {
        int row = t >> 2;
        int ch = (t & 3) * 32;
        int e = e0 + row;
        int cl = (e < N_EDGES) ? e : (N_EDGES - 1);
        int r = ei[cl], cc = ei[N_EDGES + cl];

        float rad;
        if ((t & 3) == 0) {
            float dx = coord[r * 3 + 0] - coord[cc * 3 + 0];
            float dy = coord[r * 3 + 1] - coord[cc * 3 + 1];
            float dz = coord[r * 3 + 2] - coord[cc * 3 + 2];
            rad = dx * dx + dy * dy + dz * dz;
            float inv = 1.0f / (sqrtf(rad) + 1e-8f);
            s_r[row] = r;
            s_diff[row * 3 + 0] = dx * inv;
            s_diff[row * 3 + 1] = dy * inv;
            s_diff[row * 3 + 2] = dz * inv;
        }
        rad = __shfl_sync(0xffffffffu, rad, lane & ~3);

        const float* pa = g_pa + (size_t)r * D + ch;
        const float* pb = g_pb + (size_t)cc * D + ch;
        const float* w256 = We1 + 256 * D + ch;
        uint4* ph = (uint4*)(aHi + row * PITCHA + ch);
        uint4* pl = (uint4*)(aLo + row * PITCHA + ch);
        #pragma unroll
        for (int jj = 0; jj < 4; jj++) {
            float4 a0 = *(const float4*)(pa + 8 * jj);
            float4 b0 = *(const float4*)(pb + 8 * jj);
            float4 w0 = *(const float4*)(w256 + 8 * jj);
            float4 a1 = *(const float4*)(pa + 8 * jj + 4);
            float4 b1 = *(const float4*)(pb + 8 * jj + 4);
            float4 w1 = *(const float4*)(w256 + 8 * jj + 4);
            float u0 = silu(a0.x + b0.x + rad * w0.x);
            float u1 = silu(a0.y + b0.y + rad * w0.y);
            float u2 = silu(a0.z + b0.z + rad * w0.z);
            float u3 = silu(a0.w + b0.w + rad * w0.w);
            float u4 = silu(a1.x + b1.x + rad * w1.x);
            float u5 = silu(a1.y + b1.y + rad * w1.y);
            float u6 = silu(a1.z + b1.z + rad * w1.z);
            float u7 = silu(a1.w + b1.w + rad * w1.w);
            __nv_bfloat162 ha, la, hb, lb, hc, lc, hd, ld;
            split_pair(u0, u1, ha, la);
            split_pair(u2, u3, hb, lb);
            split_pair(u4, u5, hc, lc);
            split_pair(u6, u7, hd, ld);
            uint4 HV, LV;
            HV.x = bf2_as_u32(ha); HV.y = bf2_as_u32(hb);
            HV.z = bf2_as_u32(hc); HV.w = bf2_as_u32(hd);
            LV.x = bf2_as_u32(la); LV.y = bf2_as_u32(lb);
            LV.z = bf2_as_u32(lc); LV.w = bf2_as_u32(ld);
            ph[jj] = HV;
            pl[jj] = LV;
        }
    }
    __syncthreads();

    float c[2][4][4];
    #pragma unroll
    for (int mt = 0; mt < 2; mt++)
        #pragma unroll
        for (int nt = 0; nt < 4; nt++)
            #pragma unroll
            for (int j = 0; j < 4; j++) c[mt][nt][j] = 0.f;

    int q = lane >> 2;
    int kq = 2 * (lane & 3);

    // ============ LAYER 2: act1 @ We2 -> m_ij ============
    gemm_tile64(c, aHi_addr, 16, cg, rg, lane);
    __syncthreads();
    #pragma unroll
    for (int mt = 0; mt < 2; mt++) {
        int row0 = rg * 32 + mt * 16 + q;
        int row1 = row0 + 8;
        bool v0 = (e0 + row0) < N_EDGES, v1 = (e0 + row1) < N_EDGES;
        int n0 = s_r[row0], n1 = s_r[row1];
        #pragma unroll
        for (int nt = 0; nt < 4; nt++) {
            int col = cg * 32 + nt * 8 + kq;
            float b0 = s_be2[col], b1 = s_be2[col + 1];
            float v00 = silu(c[mt][nt][0] + b0);
            float v01 = silu(c[mt][nt][1] + b1);
            float v10 = silu(c[mt][nt][2] + b0);
            float v11 = silu(c[mt][nt][3] + b1);
            __nv_bfloat162 h2, l2;
            split_pair(v00, v01, h2, l2);
            *(__nv_bfloat162*)(aHi + row0 * PITCHA + col) = h2;
            *(__nv_bfloat162*)(aLo + row0 * PITCHA + col) = l2;
            split_pair(v10, v11, h2, l2);
            *(__nv_bfloat162*)(aHi + row1 * PITCHA + col) = h2;
            *(__nv_bfloat162*)(aLo + row1 * PITCHA + col) = l2;
            if (v0) red_add_v2(&g_mi[n0 * D + col], v00, v01);
            if (v1) red_add_v2(&g_mi[n1 * D + col], v10, v11);
            c[mt][nt][0] = c[mt][nt][1] = c[mt][nt][2] = c[mt][nt][3] = 0.f;
        }
    }
    __syncthreads();

    // ============ LAYER 3: m_ij @ Wc1 -> per-edge weight ============
    gemm_tile64(c, aHi_addr, 24, cg, rg, lane);
    __syncthreads();
    #pragma unroll
    for (int mt = 0; mt < 2; mt++) {
        float p0 = 0.f, p1 = 0.f;
        #pragma unroll
        for (int nt = 0; nt < 4; nt++) {
            int col = cg * 32 + nt * 8 + kq;
            float b0 = s_bc1[col], b1 = s_bc1[col + 1];
            float w0 = s_wc2[col], w1 = s_wc2[col + 1];
            p0 = fmaf(silu(c[mt][nt][0] + b0), w0, p0);
            p0 = fmaf(silu(c[mt][nt][1] + b1), w1, p0);
            p1 = fmaf(silu(c[mt][nt][2] + b0), w0, p1);
            p1 = fmaf(silu(c[mt][nt][3] + b1), w1, p1);
        }
        p0 += __shfl_xor_sync(0xffffffffu, p0, 1);
        p0 += __shfl_xor_sync(0xffffffffu, p0, 2);
        p1 += __shfl_xor_sync(0xffffffffu, p1, 1);
        p1 += __shfl_xor_sync(0xffffffffu, p1, 2);
        if ((lane & 3) == 0) {
            int row0 = rg * 32 + mt * 16 + q;
            s_wp[row0 * 4 + cg]       = p0;
            s_wp[(row0 + 8) * 4 + cg] = p1;
        }
    }
    __syncthreads();

    if (t < 64 && (e0 + t) < N_EDGES) {
        float w = s_wp[t * 4] + s_wp[t * 4 + 1] + s_wp[t * 4 + 2] + s_wp[t * 4 + 3] + bc2[0];
        int rr = s_r[t];
        atomicAdd(&coord_out[rr * 3 + 0], s_diff[t * 3 + 0] * w);
        atomicAdd(&coord_out[rr * 3 + 1], s_diff[t * 3 + 1] * w);
        atomicAdd(&coord_out[rr * 3 + 2], s_diff[t * 3 + 2] * w);
    }
}

// ---------------------------------------------------------------------------
// node_post: HMMA. [h,m_i]@Wn1 -> silu -> @Wn2  (packed stage stores)
__global__ __launch_bounds__(256, 2) void node_post_kernel(
    const float* __restrict__ h,
    const float* __restrict__ bn1, const float* __restrict__ bn2,
    float* __restrict__ h_out)
{
    extern __shared__ __align__(16) char smem[];
    __nv_bfloat16* aHi = (__nv_bfloat16*)smem;
    __nv_bfloat16* aLo = aHi + PLANE;
    float* s_bn1 = (float*)(smem + 69632);
    float* s_bn2 = s_bn1 + 128;

    int t = threadIdx.x;
    int lane = t & 31, wid = t >> 5;
    int cg = wid & 3, rg = wid >> 2;
    int n0 = blockIdx.x * 128;
    uint32_t aHi_addr = smem_u32(aHi);

    if (t < 128) { s_bn1[t] = bn1[t]; s_bn2[t] = bn2[t]; }

    float c[4][4][4];
    #pragma unroll
    for (int mt = 0; mt < 4; mt++)
        #pragma unroll
        for (int nt = 0; nt < 4; nt++)
            #pragma unroll
            for (int j = 0; j < 4; j++) c[mt][nt][j] = 0.f;

    int q = lane >> 2;
    int kq = 2 * (lane & 3);

    auto stage_rows = [&](const float* base) {
        int r = t >> 1;
        int node = n0 + r; if (node >= N_NODES) node = N_NODES - 1;
        int ch = (t & 1) * 64;
        const float* src = base + node * D + ch;
        uint4* ph = (uint4*)(aHi + r * PITCHA + ch);
        uint4* pl = (uint4*)(aLo + r * PITCHA + ch);
        #pragma unroll
        for (int jj = 0; jj < 8; jj++) {
            float4 v0 = *(const float4*)(src + 8 * jj);
            float4 v1 = *(const float4*)(src + 8 * jj + 4);
            __nv_bfloat162 ha, la, hb, lb, hc, lc, hd, ld;
            split_pair(v0.x, v0.y, ha, la);
            split_pair(v0.z, v0.w, hb, lb);
            split_pair(v1.x, v1.y, hc, lc);
            split_pair(v1.z, v1.w, hd, ld);
            uint4 HV, LV;
            HV.x = bf2_as_u32(ha); HV.y = bf2_as_u32(hb);
            HV.z = bf2_as_u32(hc); HV.w = bf2_as_u32(hd);
            LV.x = bf2_as_u32(la); LV.y = bf2_as_u32(lb);
            LV.z = bf2_as_u32(lc); LV.w = bf2_as_u32(ld);
            ph[jj] = HV;
            pl[jj] = LV;
        }
    };

    stage_rows(h);
    __syncthreads();
    gemm_tile(c, aHi_addr, 32, cg, rg, lane);
    __syncthreads();
    stage_rows(g_mi);
    __syncthreads();
    gemm_tile(c, aHi_addr, 40, cg, rg, lane);
    __syncthreads();

    #pragma unroll
    for (int mt = 0; mt < 4; mt++) {
        int row0 = rg * 64 + mt * 16 + q;
        int row1 = row0 + 8;
        #pragma unroll
        for (int nt = 0; nt < 4; nt++) {
            int col = cg * 32 + nt * 8 + kq;
            float b0 = s_bn1[col], b1 = s_bn1[col + 1];
            float v00 = silu(c[mt][nt][0] + b0);
            float v01 = silu(c[mt][nt][1] + b1);
            float v10 = silu(c[mt][nt][2] + b0);
            float v11 = silu(c[mt][nt][3] + b1);
            __nv_bfloat162 h2, l2;
            split_pair(v00, v01, h2, l2);
            *(__nv_bfloat162*)(aHi + row0 * PITCHA + col) = h2;
            *(__nv_bfloat162*)(aLo + row0 * PITCHA + col) = l2;
            split_pair(v10, v11, h2, l2);
            *(__nv_bfloat162*)(aHi + row1 * PITCHA + col) = h2;
            *(__nv_bfloat162*)(aLo + row1 * PITCHA + col) = l2;
            c[mt][nt][0] = c[mt][nt][1] = c[mt][nt][2] = c[mt][nt][3] = 0.f;
        }
    }
    __syncthreads();

    gemm_tile(c, aHi_addr, 48, cg, rg, lane);

    #pragma unroll
    for (int mt = 0; mt < 4; mt++) {
        int row0 = rg * 64 + mt * 16 + q;
        int row1 = row0 + 8;
        bool v0 = (n0 + row0) < N_NODES, v1 = (n0 + row1) < N_NODES;
        #pragma unroll
        for (int nt = 0; nt < 4; nt++) {
            int col = cg * 32 + nt * 8 + kq;
            float b0 = s_bn2[col], b1 = s_bn2[col + 1];
            if (v0) {
                float2 o = make_float2(c[mt][nt][0] + b0, c[mt][nt][1] + b1);
                *(float2*)&h_out[(n0 + row0) * D + col] = o;
            }
            if (v1) {
                float2 o = make_float2(c[mt][nt][2] + b0, c[mt][nt][3] + b1);
                *(float2*)&h_out[(n0 + row1) * D + col] = o;
            }
        }
    }
}

// ---------------------------------------------------------------------------
extern "C" void kernel_launch(void* const* d_in, const int* in_sizes, int n_in,
                              void* d_out, int out_size)
{
    const float* h     = (const float*)d_in[0];
    const float* coord = (const float*)d_in[1];
    const float* vel   = (const float*)d_in[2];
    const int*   ei    = (const int*)  d_in[3];
    const float* We1 = (const float*)d_in[4];  const float* be1 = (const float*)d_in[5];
    const float* We2 = (const float*)d_in[6];  const float* be2 = (const float*)d_in[7];
    const float* Wc1 = (const float*)d_in[8];  const float* bc1 = (const float*)d_in[9];
    const float* Wc2 = (const float*)d_in[10]; const float* bc2 = (const float*)d_in[11];
    const float* Wv1 = (const float*)d_in[12]; const float* bv1 = (const float*)d_in[13];
    const float* Wv2 = (const float*)d_in[14]; const float* bv2 = (const float*)d_in[15];
    const float* Wn1 = (const float*)d_in[16]; const float* bn1 = (const float*)d_in[17];
    const float* Wn2 = (const float*)d_in[18]; const float* bn2 = (const float*)d_in[19];

    float* h_out     = (float*)d_out;                  // [N, 128]
    float* coord_out = (float*)d_out + N_NODES * D;    // [N, 3]

    cudaFuncSetAttribute(edge_kernel, cudaFuncAttributeMaxDynamicSharedMemorySize, EDGE_SMEM);
    cudaFuncSetAttribute(node_post_kernel, cudaFuncAttributeMaxDynamicSharedMemorySize, BIG_SMEM);
    cudaFuncSetAttribute(pab_kernel, cudaFuncAttributeMaxDynamicSharedMemorySize, BIG_SMEM);

    int edge_blocks = (N_EDGES + 63) / 64;
    int nblk128 = (N_NODES + 127) / 128;

    zero_mi_kernel<<<(N_NODES * D / 4 + 255) / 256, 256>>>();
    prep_bimg_kernel<<<(64 * 16 * 32 + 255) / 256, 256>>>(We1, We2, Wc1, Wn1, Wn2, Wv1);
    pab_kernel<<<nblk128, 256, BIG_SMEM>>>(h, be1, coord, vel, bv1, Wv2, bv2, coord_out);
    edge_kernel<<<edge_blocks, 256, EDGE_SMEM>>>(coord, ei,
                                                 be2, bc1, Wc2, bc2, We1, coord_out);
    node_post_kernel<<<nblk128, 256, BIG_SMEM>>>(h, bn1, bn2, h_out);
}

// round 16
// speedup vs baseline: 1.0220x; 1.0220x over previous
#include <cuda_runtime.h>
#include <cuda_bf16.h>
#include <cstdint>
#include <cstring>

#define N_NODES 50000
#define N_EDGES 500000
#define D 128

#define PITCHA 136   // HMMA activation plane pitch (bf16 elements)
#define PLANE   (128 * PITCHA)
#define PLANE64 (64 * PITCHA)

// ---------------- scratch (static device globals: allowed) ----------------
__device__ float g_mi[N_NODES * D];
__device__ float g_pa[N_NODES * D];   // h @ We1[0:128)   + be1
__device__ float g_pb[N_NODES * D];   // h @ We1[128:256)
// fragment-ordered weight image: 64 ktile-slots x 16 ntiles x 32 lanes x uint4
// 0-7 We1[0:128), 8-15 We1[128:256), 16-23 We2, 24-31 Wc1,
// 32-39 Wn1[0:128), 40-47 Wn1[128:256), 48-55 Wn2, 56-63 Wv1
__device__ uint4 g_bimg[64 * 16 * 32];

__device__ __forceinline__ float silu(float x) { return x / (1.0f + __expf(-x)); }

__device__ __forceinline__ uint32_t bf2_as_u32(__nv_bfloat162 v) {
    uint32_t u; memcpy(&u, &v, 4); return u;
}
__device__ __forceinline__ uint32_t smem_u32(const void* p) {
    uint32_t a;
    asm("{ .reg .u64 t; cvta.to.shared.u64 t, %1; cvt.u32.u64 %0, t; }" : "=r"(a) : "l"(p));
    return a;
}

__device__ __forceinline__ void mma_bf16(
    float* c, uint32_t a0, uint32_t a1, uint32_t a2, uint32_t a3,
    uint32_t b0, uint32_t b1)
{
    asm volatile(
        "mma.sync.aligned.m16n8k16.row.col.f32.bf16.bf16.f32 "
        "{%0,%1,%2,%3}, {%4,%5,%6,%7}, {%8,%9}, {%0,%1,%2,%3};"
        : "+f"(c[0]), "+f"(c[1]), "+f"(c[2]), "+f"(c[3])
        : "r"(a0), "r"(a1), "r"(a2), "r"(a3), "r"(b0), "r"(b1));
}

__device__ __forceinline__ void ldsm_x4(
    uint32_t& r0, uint32_t& r1, uint32_t& r2, uint32_t& r3, uint32_t addr)
{
    asm volatile("ldmatrix.sync.aligned.m8n8.x4.shared.b16 {%0,%1,%2,%3}, [%4];"
                 : "=r"(r0), "=r"(r1), "=r"(r2), "=r"(r3) : "r"(addr));
}

__device__ __forceinline__ void split_pair(
    float x, float y, __nv_bfloat162& hi, __nv_bfloat162& lo)
{
    hi = __floats2bfloat162_rn(x, y);
    lo = __floats2bfloat162_rn(x - __low2float(hi), y - __high2float(hi));
}

// packed f32 pair reduction (sm_90+ baseline): 8B-aligned dst required
__device__ __forceinline__ void red_add_v2(float* p, float a, float b) {
    asm volatile("red.global.add.v2.f32 [%0], {%1, %2};"
                 :: "l"(p), "f"(a), "f"(b) : "memory");
}

// ---------------------------------------------------------------------------
__global__ void zero_mi_kernel() {
    int i = blockIdx.x * blockDim.x + threadIdx.x;
    if (i < N_NODES * D / 4)
        reinterpret_cast<float4*>(g_mi)[i] = make_float4(0.f, 0.f, 0.f, 0.f);
}

// ---------------------------------------------------------------------------
__global__ void prep_bimg_kernel(
    const float* __restrict__ We1, const float* __restrict__ We2,
    const float* __restrict__ Wc1, const float* __restrict__ Wn1,
    const float* __restrict__ Wn2, const float* __restrict__ Wv1)
{
    int idx = blockIdx.x * 256 + threadIdx.x;
    if (idx >= 64 * 16 * 32) return;
    int lane = idx & 31;
    int nt = (idx >> 5) & 15;
    int s = idx >> 9;
    int col = nt * 8 + (lane >> 2);
    int kloc = 2 * (lane & 3);
    const float* W; int kr;
    if (s < 8)       { W = We1; kr = s * 16 + kloc; }
    else if (s < 16) { W = We1; kr = 128 + (s - 8) * 16 + kloc; }
    else if (s < 24) { W = We2; kr = (s - 16) * 16 + kloc; }
    else if (s < 32) { W = Wc1; kr = (s - 24) * 16 + kloc; }
    else if (s < 40) { W = Wn1; kr = (s - 32) * 16 + kloc; }
    else if (s < 48) { W = Wn1; kr = 128 + (s - 40) * 16 + kloc; }
    else if (s < 56) { W = Wn2; kr = (s - 48) * 16 + kloc; }
    else             { W = Wv1; kr = (s - 56) * 16 + kloc; }
    float f00 = W[kr * D + col];
    float f01 = W[(kr + 1) * D + col];
    float f10 = W[(kr + 8) * D + col];
    float f11 = W[(kr + 9) * D + col];
    __nv_bfloat162 h0, l0, h1, l1;
    split_pair(f00, f01, h0, l0);
    split_pair(f10, f11, h1, l1);
    uint4 v;
    v.x = bf2_as_u32(h0); v.y = bf2_as_u32(h1);
    v.z = bf2_as_u32(l0); v.w = bf2_as_u32(l1);
    g_bimg[idx] = v;
}

// ---------------------------------------------------------------------------
// 128-row software-pipelined warp-tile GEMM (3-pass hi/lo bf16) — pab
__device__ __forceinline__ void gemm_tile(
    float (&c)[4][4][4], uint32_t aHi_addr, int base,
    int cg, int rg, int lane)
{
    int lrow = lane & 15;
    int lcol = (lane >> 4) * 8;
    const uint4* bp = g_bimg + (base * 16 + cg * 4) * 32 + lane;
    uint4 b[4], bn[4];
    #pragma unroll
    for (int nt = 0; nt < 4; nt++) b[nt] = __ldg(bp + nt * 32);
    uint32_t abase = aHi_addr + (uint32_t)(((rg * 64 + lrow) * PITCHA + lcol) * 2);
    uint32_t ah[2][4], al[2][4];
    ldsm_x4(ah[0][0], ah[0][1], ah[0][2], ah[0][3], abase);
    ldsm_x4(al[0][0], al[0][1], al[0][2], al[0][3], abase + PLANE * 2);
    #pragma unroll
    for (int kt = 0; kt < 8; kt++) {
        if (kt < 7) {
            #pragma unroll
            for (int nt = 0; nt < 4; nt++) bn[nt] = __ldg(bp + 16 * 32 + nt * 32);
        }
        #pragma unroll
        for (int mt = 0; mt < 4; mt++) {
            int cur = mt & 1, nxt = 1 - cur;
            if (mt < 3) {
                uint32_t addr = abase + (uint32_t)((((mt + 1) * 16) * PITCHA + kt * 16) * 2);
                ldsm_x4(ah[nxt][0], ah[nxt][1], ah[nxt][2], ah[nxt][3], addr);
                ldsm_x4(al[nxt][0], al[nxt][1], al[nxt][2], al[nxt][3], addr + PLANE * 2);
            } else if (kt < 7) {
                uint32_t addr = abase + (uint32_t)(((kt + 1) * 16) * 2);
                ldsm_x4(ah[nxt][0], ah[nxt][1], ah[nxt][2], ah[nxt][3], addr);
                ldsm_x4(al[nxt][0], al[nxt][1], al[nxt][2], al[nxt][3], addr + PLANE * 2);
            }
            #pragma unroll
            for (int nt = 0; nt < 4; nt++) {
                mma_bf16(c[mt][nt], ah[cur][0], ah[cur][1], ah[cur][2], ah[cur][3], b[nt].x, b[nt].y);
                mma_bf16(c[mt][nt], ah[cur][0], ah[cur][1], ah[cur][2], ah[cur][3], b[nt].z, b[nt].w);
                mma_bf16(c[mt][nt], al[cur][0], al[cur][1], al[cur][2], al[cur][3], b[nt].x, b[nt].y);
            }
        }
        #pragma unroll
        for (int nt = 0; nt < 4; nt++) b[nt] = bn[nt];
        bp += 16 * 32;
    }
}

// 64-row warp-tile GEMM (32 accumulators) — edge + node_post, 3 blocks/SM
__device__ __forceinline__ void gemm_tile64(
    float (&c)[2][4][4], uint32_t aHi_addr, int base,
    int cg, int rg, int lane)
{
    int lrow = lane & 15;
    int lcol = (lane >> 4) * 8;
    const uint4* bp = g_bimg + (base * 16 + cg * 4) * 32 + lane;
    uint32_t abase = aHi_addr + (uint32_t)(((rg * 32 + lrow) * PITCHA + lcol) * 2);
    #pragma unroll
    for (int kt = 0; kt < 8; kt++) {
        uint4 b[4];
        #pragma unroll
        for (int nt = 0; nt < 4; nt++) b[nt] = __ldg(bp + nt * 32);
        #pragma unroll
        for (int mt = 0; mt < 2; mt++) {
            uint32_t addr = abase + (uint32_t)(((mt * 16) * PITCHA + kt * 16) * 2);
            uint32_t ah0, ah1, ah2, ah3, al0, al1, al2, al3;
            ldsm_x4(ah0, ah1, ah2, ah3, addr);
            ldsm_x4(al0, al1, al2, al3, addr + PLANE64 * 2);
            #pragma unroll
            for (int nt = 0; nt < 4; nt++) {
                mma_bf16(c[mt][nt], ah0, ah1, ah2, ah3, b[nt].x, b[nt].y);
                mma_bf16(c[mt][nt], ah0, ah1, ah2, ah3, b[nt].z, b[nt].w);
                mma_bf16(c[mt][nt], al0, al1, al2, al3, b[nt].x, b[nt].y);
            }
        }
        bp += 16 * 32;
    }
}

#define BIG_SMEM  75776   // pab (128-row planes)
#define EDGE_SMEM 37632   // edge / node_post (64-row planes)

// ---------------------------------------------------------------------------
// pab_kernel (verified R11-R13): P_A, P_B, vel weights + coord base
__global__ __launch_bounds__(256, 2) void pab_kernel(
    const float* __restrict__ h, const float* __restrict__ be1,
    const float* __restrict__ coord, const float* __restrict__ vel,
    const float* __restrict__ bv1, const float* __restrict__ Wv2,
    const float* __restrict__ bv2,
    float* __restrict__ coord_out)
{
    extern __shared__ __align__(16) char smem[];
    __nv_bfloat16* aHi = (__nv_bfloat16*)smem;
    __nv_bfloat16* aLo = aHi + PLANE;
    float* s_be1 = (float*)(smem + 69632);
    float* s_bv1 = s_be1 + 128;
    float* s_wv2 = s_bv1 + 128;
    float* s_wp  = (float*)smem;

    int t = threadIdx.x;
    int lane = t & 31, wid = t >> 5;
    int cg = wid & 3, rg = wid >> 2;
    int n0 = blockIdx.x * 128;
    uint32_t aHi_addr = smem_u32(aHi);

    if (t < 128) { s_be1[t] = be1[t]; s_bv1[t] = bv1[t]; s_wv2[t] = Wv2[t]; }

    {
        int r = t >> 1;
        int node = n0 + r; if (node >= N_NODES) node = N_NODES - 1;
        int ch = (t & 1) * 64;
        const float* src = h + node * D + ch;
        __nv_bfloat16* ph = aHi + r * PITCHA + ch;
        __nv_bfloat16* pl = aLo + r * PITCHA + ch;
        #pragma unroll
        for (int j = 0; j < 16; j++) {
            float4 v = *(const float4*)(src + 4 * j);
            __nv_bfloat162 h2a, l2a, h2b, l2b;
            split_pair(v.x, v.y, h2a, l2a);
            split_pair(v.z, v.w, h2b, l2b);
            *(__nv_bfloat162*)(ph + 4 * j)     = h2a;
            *(__nv_bfloat162*)(ph + 4 * j + 2) = h2b;
            *(__nv_bfloat162*)(pl + 4 * j)     = l2a;
            *(__nv_bfloat162*)(pl + 4 * j + 2) = l2b;
        }
    }
    __syncthreads();

    float c[4][4][4];
    #pragma unroll
    for (int mt = 0; mt < 4; mt++)
        #pragma unroll
        for (int nt = 0; nt < 4; nt++)
            #pragma unroll
            for (int j = 0; j < 4; j++) c[mt][nt][j] = 0.f;

    int q = lane >> 2;
    int kq = 2 * (lane & 3);

    gemm_tile(c, aHi_addr, 0, cg, rg, lane);
    #pragma unroll
    for (int mt = 0; mt < 4; mt++) {
        int row0 = rg * 64 + mt * 16 + q;
        int row1 = row0 + 8;
        bool v0 = (n0 + row0) < N_NODES, v1 = (n0 + row1) < N_NODES;
        #pragma unroll
        for (int nt = 0; nt < 4; nt++) {
            int col = cg * 32 + nt * 8 + kq;
            float b0 = s_be1[col], b1 = s_be1[col + 1];
            if (v0) *(float2*)&g_pa[(n0 + row0) * D + col] =
                make_float2(c[mt][nt][0] + b0, c[mt][nt][1] + b1);
            if (v1) *(float2*)&g_pa[(n0 + row1) * D + col] =
                make_float2(c[mt][nt][2] + b0, c[mt][nt][3] + b1);
            c[mt][nt][0] = c[mt][nt][1] = c[mt][nt][2] = c[mt][nt][3] = 0.f;
        }
    }
    gemm_tile(c, aHi_addr, 8, cg, rg, lane);
    #pragma unroll
    for (int mt = 0; mt < 4; mt++) {
        int row0 = rg * 64 + mt * 16 + q;
        int row1 = row0 + 8;
        bool v0 = (n0 + row0) < N_NODES, v1 = (n0 + row1) < N_NODES;
        #pragma unroll
        for (int nt = 0; nt < 4; nt++) {
            int col = cg * 32 + nt * 8 + kq;
            if (v0) *(float2*)&g_pb[(n0 + row0) * D + col] =
                make_float2(c[mt][nt][0], c[mt][nt][1]);
            if (v1) *(float2*)&g_pb[(n0 + row1) * D + col] =
                make_float2(c[mt][nt][2], c[mt][nt][3]);
            c[mt][nt][0] = c[mt][nt][1] = c[mt][nt][2] = c[mt][nt][3] = 0.f;
        }
    }
    gemm_tile(c, aHi_addr, 56, cg, rg, lane);
    __syncthreads();
    #pragma unroll
    for (int mt = 0; mt < 4; mt++) {
        float p0 = 0.f, p1 = 0.f;
        #pragma unroll
        for (int nt = 0; nt < 4; nt++) {
            int col = cg * 32 + nt * 8 + kq;
            float b0 = s_bv1[col], b1 = s_bv1[col + 1];
            float w0 = s_wv2[col], w1 = s_wv2[col + 1];
            p0 = fmaf(silu(c[mt][nt][0] + b0), w0, p0);
            p0 = fmaf(silu(c[mt][nt][1] + b1), w1, p0);
            p1 = fmaf(silu(c[mt][nt][2] + b0), w0, p1);
            p1 = fmaf(silu(c[mt][nt][3] + b1), w1, p1);
        }
        p0 += __shfl_xor_sync(0xffffffffu, p0, 1);
        p0 += __shfl_xor_sync(0xffffffffu, p0, 2);
        p1 += __shfl_xor_sync(0xffffffffu, p1, 1);
        p1 += __shfl_xor_sync(0xffffffffu, p1, 2);
        if ((lane & 3) == 0) {
            int row0 = rg * 64 + mt * 16 + q;
            s_wp[row0 * 4 + cg]       = p0;
            s_wp[(row0 + 8) * 4 + cg] = p1;
        }
    }
    __syncthreads();
    if (t < 128 && (n0 + t) < N_NODES) {
        float vw = s_wp[t * 4] + s_wp[t * 4 + 1] + s_wp[t * 4 + 2] + s_wp[t * 4 + 3] + bv2[0];
        int n = n0 + t;
        #pragma unroll
        for (int i = 0; i < 3; i++)
            coord_out[n * 3 + i] = coord[n * 3 + i] + vel[n * 3 + i] * vw;
    }
}

// ---------------------------------------------------------------------------
// edge kernel: 64 edges/block, 32-acc warp tiles, 3 blocks/SM (R13-exact)
__global__ __launch_bounds__(256, 3) void edge_kernel(
    const float* __restrict__ coord,
    const int* __restrict__ ei,
    const float* __restrict__ be2,
    const float* __restrict__ bc1,
    const float* __restrict__ Wc2, const float* __restrict__ bc2,
    const float* __restrict__ We1,
    float* __restrict__ coord_out)
{
    extern __shared__ __align__(16) char smem[];
    __nv_bfloat16* aHi = (__nv_bfloat16*)smem;              // 17408 B
    __nv_bfloat16* aLo = aHi + PLANE64;                     // 17408 B
    float* s_be2  = (float*)(smem + 34816);
    float* s_bc1  = s_be2 + 128;
    float* s_wc2  = s_bc1 + 128;
    int*   s_r    = (int*)(smem + 36352);    // 64 ints
    float* s_diff = (float*)(smem + 36608);  // 64*3 floats
    float* s_wp   = (float*)smem;            // L3 partials alias plane

    int t = threadIdx.x;
    int lane = t & 31, wid = t >> 5;
    int cg = wid & 3, rg = wid >> 2;        // rg in {0,1}
    int e0 = blockIdx.x * 64;

    uint32_t aHi_addr = smem_u32(aHi);

    if (t < 128) { s_be2[t] = be2[t]; s_bc1[t] = bc1[t]; s_wc2[t] = Wc2[t]; }

    // ---- per-thread gather + act1 (256 threads, 64 rows x 4 chunks of 32) ----
    {
        int row = t >> 2;
        int ch = (t & 3) * 32;
        int e = e0 + row;
        int cl = (e < N_EDGES) ? e : (N_EDGES - 1);
        int r = ei[cl], cc = ei[N_EDGES + cl];

        float rad;
        if ((t & 3) == 0) {
            float dx = coord[r * 3 + 0] - coord[cc * 3 + 0];
            float dy = coord[r * 3 + 1] - coord[cc * 3 + 1];
            float dz = coord[r * 3 + 2] - coord[cc * 3 + 2];
            rad = dx * dx + dy * dy + dz * dz;
            float inv = 1.0f / (sqrtf(rad) + 1e-8f);
            s_r[row] = r;
            s_diff[row * 3 + 0] = dx * inv;
            s_diff[row * 3 + 1] = dy * inv;
            s_diff[row * 3 + 2] = dz * inv;
        }
        rad = __shfl_sync(0xffffffffu, rad, lane & ~3);

        const float* pa = g_pa + (size_t)r * D + ch;
        const float* pb = g_pb + (size_t)cc * D + ch;
        const float* w256 = We1 + 256 * D + ch;
        __nv_bfloat16* ph = aHi + row * PITCHA + ch;
        __nv_bfloat16* pl = aLo + row * PITCHA + ch;
        #pragma unroll
        for (int j = 0; j < 8; j++) {
            float4 a = *(const float4*)(pa + 4 * j);
            float4 b = *(const float4*)(pb + 4 * j);
            float4 w = *(const float4*)(w256 + 4 * j);
            float v0 = silu(a.x + b.x + rad * w.x);
            float v1 = silu(a.y + b.y + rad * w.y);
            float v2 = silu(a.z + b.z + rad * w.z);
            float v3 = silu(a.w + b.w + rad * w.w);
            __nv_bfloat162 h2a, l2a, h2b, l2b;
            split_pair(v0, v1, h2a, l2a);
            split_pair(v2, v3, h2b, l2b);
            *(__nv_bfloat162*)(ph + 4 * j)     = h2a;
            *(__nv_bfloat162*)(ph + 4 * j + 2) = h2b;
            *(__nv_bfloat162*)(pl + 4 * j)     = l2a;
            *(__nv_bfloat162*)(pl + 4 * j + 2) = l2b;
        }
    }
    __syncthreads();

    float c[2][4][4];
    #pragma unroll
    for (int mt = 0; mt < 2; mt++)
        #pragma unroll
        for (int nt = 0; nt < 4; nt++)
            #pragma unroll
            for (int j = 0; j < 4; j++) c[mt][nt][j] = 0.f;

    int q = lane >> 2;
    int kq = 2 * (lane & 3);

    // ============ LAYER 2: act1 @ We2 -> m_ij ============
    gemm_tile64(c, aHi_addr, 16, cg, rg, lane);
    __syncthreads();
    #pragma unroll
    for (int mt = 0; mt < 2; mt++) {
        int row0 = rg * 32 + mt * 16 + q;
        int row1 = row0 + 8;
        bool v0 = (e0 + row0) < N_EDGES, v1 = (e0 + row1) < N_EDGES;
        int n0 = s_r[row0], n1 = s_r[row1];
        #pragma unroll
        for (int nt = 0; nt < 4; nt++) {
            int col = cg * 32 + nt * 8 + kq;
            float b0 = s_be2[col], b1 = s_be2[col + 1];
            float v00 = silu(c[mt][nt][0] + b0);
            float v01 = silu(c[mt][nt][1] + b1);
            float v10 = silu(c[mt][nt][2] + b0);
            float v11 = silu(c[mt][nt][3] + b1);
            __nv_bfloat162 h2, l2;
            split_pair(v00, v01, h2, l2);
            *(__nv_bfloat162*)(aHi + row0 * PITCHA + col) = h2;
            *(__nv_bfloat162*)(aLo + row0 * PITCHA + col) = l2;
            split_pair(v10, v11, h2, l2);
            *(__nv_bfloat162*)(aHi + row1 * PITCHA + col) = h2;
            *(__nv_bfloat162*)(aLo + row1 * PITCHA + col) = l2;
            if (v0) red_add_v2(&g_mi[n0 * D + col], v00, v01);
            if (v1) red_add_v2(&g_mi[n1 * D + col], v10, v11);
            c[mt][nt][0] = c[mt][nt][1] = c[mt][nt][2] = c[mt][nt][3] = 0.f;
        }
    }
    __syncthreads();

    // ============ LAYER 3: m_ij @ Wc1 -> per-edge weight ============
    gemm_tile64(c, aHi_addr, 24, cg, rg, lane);
    __syncthreads();
    #pragma unroll
    for (int mt = 0; mt < 2; mt++) {
        float p0 = 0.f, p1 = 0.f;
        #pragma unroll
        for (int nt = 0; nt < 4; nt++) {
            int col = cg * 32 + nt * 8 + kq;
            float b0 = s_bc1[col], b1 = s_bc1[col + 1];
            float w0 = s_wc2[col], w1 = s_wc2[col + 1];
            p0 = fmaf(silu(c[mt][nt][0] + b0), w0, p0);
            p0 = fmaf(silu(c[mt][nt][1] + b1), w1, p0);
            p1 = fmaf(silu(c[mt][nt][2] + b0), w0, p1);
            p1 = fmaf(silu(c[mt][nt][3] + b1), w1, p1);
        }
        p0 += __shfl_xor_sync(0xffffffffu, p0, 1);
        p0 += __shfl_xor_sync(0xffffffffu, p0, 2);
        p1 += __shfl_xor_sync(0xffffffffu, p1, 1);
        p1 += __shfl_xor_sync(0xffffffffu, p1, 2);
        if ((lane & 3) == 0) {
            int row0 = rg * 32 + mt * 16 + q;
            s_wp[row0 * 4 + cg]       = p0;
            s_wp[(row0 + 8) * 4 + cg] = p1;
        }
    }
    __syncthreads();

    if (t < 64 && (e0 + t) < N_EDGES) {
        float w = s_wp[t * 4] + s_wp[t * 4 + 1] + s_wp[t * 4 + 2] + s_wp[t * 4 + 3] + bc2[0];
        int rr = s_r[t];
        atomicAdd(&coord_out[rr * 3 + 0], s_diff[t * 3 + 0] * w);
        atomicAdd(&coord_out[rr * 3 + 1], s_diff[t * 3 + 1] * w);
        atomicAdd(&coord_out[rr * 3 + 2], s_diff[t * 3 + 2] * w);
    }
}

// ---------------------------------------------------------------------------
// node_post: 64 nodes/block, 3 blocks/SM (same tiling as edge kernel)
__global__ __launch_bounds__(256, 3) void node_post_kernel(
    const float* __restrict__ h,
    const float* __restrict__ bn1, const float* __restrict__ bn2,
    float* __restrict__ h_out)
{
    extern __shared__ __align__(16) char smem[];
    __nv_bfloat16* aHi = (__nv_bfloat16*)smem;              // 17408 B
    __nv_bfloat16* aLo = aHi + PLANE64;                     // 17408 B
    float* s_bn1 = (float*)(smem + 34816);
    float* s_bn2 = s_bn1 + 128;

    int t = threadIdx.x;
    int lane = t & 31, wid = t >> 5;
    int cg = wid & 3, rg = wid >> 2;        // rg in {0,1}
    int n0 = blockIdx.x * 64;
    uint32_t aHi_addr = smem_u32(aHi);

    if (t < 128) { s_bn1[t] = bn1[t]; s_bn2[t] = bn2[t]; }

    float c[2][4][4];
    #pragma unroll
    for (int mt = 0; mt < 2; mt++)
        #pragma unroll
        for (int nt = 0; nt < 4; nt++)
            #pragma unroll
            for (int j = 0; j < 4; j++) c[mt][nt][j] = 0.f;

    int q = lane >> 2;
    int kq = 2 * (lane & 3);

    auto stage_rows = [&](const float* base) {
        int row = t >> 2;
        int node = n0 + row; if (node >= N_NODES) node = N_NODES - 1;
        int ch = (t & 3) * 32;
        const float* src = base + node * D + ch;
        __nv_bfloat16* ph = aHi + row * PITCHA + ch;
        __nv_bfloat16* pl = aLo + row * PITCHA + ch;
        #pragma unroll
        for (int j = 0; j < 8; j++) {
            float4 v = *(const float4*)(src + 4 * j);
            __nv_bfloat162 h2a, l2a, h2b, l2b;
            split_pair(v.x, v.y, h2a, l2a);
            split_pair(v.z, v.w, h2b, l2b);
            *(__nv_bfloat162*)(ph + 4 * j)     = h2a;
            *(__nv_bfloat162*)(ph + 4 * j + 2) = h2b;
            *(__nv_bfloat162*)(pl + 4 * j)     = l2a;
            *(__nv_bfloat162*)(pl + 4 * j + 2) = l2b;
        }
    };

    // layer 1: [h | m_i] @ Wn1 (K=256 via two staged tiles)
    stage_rows(h);
    __syncthreads();
    gemm_tile64(c, aHi_addr, 32, cg, rg, lane);
    __syncthreads();
    stage_rows(g_mi);
    __syncthreads();
    gemm_tile64(c, aHi_addr, 40, cg, rg, lane);
    __syncthreads();

    // epilogue: silu(C + bn1) -> planes
    #pragma unroll
    for (int mt = 0; mt < 2; mt++) {
        int row0 = rg * 32 + mt * 16 + q;
        int row1 = row0 + 8;
        #pragma unroll
        for (int nt = 0; nt < 4; nt++) {
            int col = cg * 32 + nt * 8 + kq;
            float b0 = s_bn1[col], b1 = s_bn1[col + 1];
            float v00 = silu(c[mt][nt][0] + b0);
            float v01 = silu(c[mt][nt][1] + b1);
            float v10 = silu(c[mt][nt][2] + b0);
            float v11 = silu(c[mt][nt][3] + b1);
            __nv_bfloat162 h2, l2;
            split_pair(v00, v01, h2, l2);
            *(__nv_bfloat162*)(aHi + row0 * PITCHA + col) = h2;
            *(__nv_bfloat162*)(aLo + row0 * PITCHA + col) = l2;
            split_pair(v10, v11, h2, l2);
            *(__nv_bfloat162*)(aHi + row1 * PITCHA + col) = h2;
            *(__nv_bfloat162*)(aLo + row1 * PITCHA + col) = l2;
            c[mt][nt][0] = c[mt][nt][1] = c[mt][nt][2] = c[mt][nt][3] = 0.f;
        }
    }
    __syncthreads();

    // layer 2: act @ Wn2, write h_out
    gemm_tile64(c, aHi_addr, 48, cg, rg, lane);

    #pragma unroll
    for (int mt = 0; mt < 2; mt++) {
        int row0 = rg * 32 + mt * 16 + q;
        int row1 = row0 + 8;
        bool v0 = (n0 + row0) < N_NODES, v1 = (n0 + row1) < N_NODES;
        #pragma unroll
        for (int nt = 0; nt < 4; nt++) {
            int col = cg * 32 + nt * 8 + kq;
            float b0 = s_bn2[col], b1 = s_bn2[col + 1];
            if (v0) {
                float2 o = make_float2(c[mt][nt][0] + b0, c[mt][nt][1] + b1);
                *(float2*)&h_out[(n0 + row0) * D + col] = o;
            }
            if (v1) {
                float2 o = make_float2(c[mt][nt][2] + b0, c[mt][nt][3] + b1);
                *(float2*)&h_out[(n0 + row1) * D + col] = o;
            }
        }
    }
}

// ---------------------------------------------------------------------------
extern "C" void kernel_launch(void* const* d_in, const int* in_sizes, int n_in,
                              void* d_out, int out_size)
{
    const float* h     = (const float*)d_in[0];
    const float* coord = (const float*)d_in[1];
    const float* vel   = (const float*)d_in[2];
    const int*   ei    = (const int*)  d_in[3];
    const float* We1 = (const float*)d_in[4];  const float* be1 = (const float*)d_in[5];
    const float* We2 = (const float*)d_in[6];  const float* be2 = (const float*)d_in[7];
    const float* Wc1 = (const float*)d_in[8];  const float* bc1 = (const float*)d_in[9];
    const float* Wc2 = (const float*)d_in[10]; const float* bc2 = (const float*)d_in[11];
    const float* Wv1 = (const float*)d_in[12]; const float* bv1 = (const float*)d_in[13];
    const float* Wv2 = (const float*)d_in[14]; const float* bv2 = (const float*)d_in[15];
    const float* Wn1 = (const float*)d_in[16]; const float* bn1 = (const float*)d_in[17];
    const float* Wn2 = (const float*)d_in[18]; const float* bn2 = (const float*)d_in[19];

    float* h_out     = (float*)d_out;                  // [N, 128]
    float* coord_out = (float*)d_out + N_NODES * D;    // [N, 3]

    cudaFuncSetAttribute(edge_kernel, cudaFuncAttributeMaxDynamicSharedMemorySize, EDGE_SMEM);
    cudaFuncSetAttribute(node_post_kernel, cudaFuncAttributeMaxDynamicSharedMemorySize, EDGE_SMEM);
    cudaFuncSetAttribute(pab_kernel, cudaFuncAttributeMaxDynamicSharedMemorySize, BIG_SMEM);

    int edge_blocks = (N_EDGES + 63) / 64;
    int npost_blocks = (N_NODES + 63) / 64;
    int nblk128 = (N_NODES + 127) / 128;

    zero_mi_kernel<<<(N_NODES * D / 4 + 255) / 256, 256>>>();
    prep_bimg_kernel<<<(64 * 16 * 32 + 255) / 256, 256>>>(We1, We2, Wc1, Wn1, Wn2, Wv1);
    pab_kernel<<<nblk128, 256, BIG_SMEM>>>(h, be1, coord, vel, bv1, Wv2, bv2, coord_out);
    edge_kernel<<<edge_blocks, 256, EDGE_SMEM>>>(coord, ei,
                                                 be2, bc1, Wc2, bc2, We1, coord_out);
    node_post_kernel<<<npost_blocks, 256, EDGE_SMEM>>>(h, bn1, bn2, h_out);
}

// round 17
// speedup vs baseline: 1.0849x; 1.0616x over previous
#include <cuda_runtime.h>
#include <cuda_bf16.h>
#include <cstdint>
#include <cstring>

#define N_NODES 50000
#define N_EDGES 500000
#define D 128

#define PITCHA 136   // HMMA activation plane pitch (bf16 elements)
#define PLANE   (128 * PITCHA)
#define PLANE64 (64 * PITCHA)

// ---------------- scratch (static device globals: allowed) ----------------
__device__ float g_mi[N_NODES * D];
__device__ float g_pa[N_NODES * D];   // h @ We1[0:128)   + be1
__device__ float g_pb[N_NODES * D];   // h @ We1[128:256)
// fragment-ordered weight image: 64 ktile-slots x 16 ntiles x 32 lanes x uint4
// 0-7 We1[0:128), 8-15 We1[128:256), 16-23 We2, 24-31 Wc1,
// 32-39 Wn1[0:128), 40-47 Wn1[128:256), 48-55 Wn2, 56-63 Wv1
__device__ uint4 g_bimg[64 * 16 * 32];

__device__ __forceinline__ float silu(float x) { return x / (1.0f + __expf(-x)); }

__device__ __forceinline__ uint32_t bf2_as_u32(__nv_bfloat162 v) {
    uint32_t u; memcpy(&u, &v, 4); return u;
}
__device__ __forceinline__ uint32_t smem_u32(const void* p) {
    uint32_t a;
    asm("{ .reg .u64 t; cvta.to.shared.u64 t, %1; cvt.u32.u64 %0, t; }" : "=r"(a) : "l"(p));
    return a;
}

__device__ __forceinline__ void mma_bf16(
    float* c, uint32_t a0, uint32_t a1, uint32_t a2, uint32_t a3,
    uint32_t b0, uint32_t b1)
{
    asm volatile(
        "mma.sync.aligned.m16n8k16.row.col.f32.bf16.bf16.f32 "
        "{%0,%1,%2,%3}, {%4,%5,%6,%7}, {%8,%9}, {%0,%1,%2,%3};"
        : "+f"(c[0]), "+f"(c[1]), "+f"(c[2]), "+f"(c[3])
        : "r"(a0), "r"(a1), "r"(a2), "r"(a3), "r"(b0), "r"(b1));
}

__device__ __forceinline__ void ldsm_x4(
    uint32_t& r0, uint32_t& r1, uint32_t& r2, uint32_t& r3, uint32_t addr)
{
    asm volatile("ldmatrix.sync.aligned.m8n8.x4.shared.b16 {%0,%1,%2,%3}, [%4];"
                 : "=r"(r0), "=r"(r1), "=r"(r2), "=r"(r3) : "r"(addr));
}

__device__ __forceinline__ void split_pair(
    float x, float y, __nv_bfloat162& hi, __nv_bfloat162& lo)
{
    hi = __floats2bfloat162_rn(x, y);
    lo = __floats2bfloat162_rn(x - __low2float(hi), y - __high2float(hi));
}

// packed f32 pair reduction (sm_90+ baseline): 8B-aligned dst required
__device__ __forceinline__ void red_add_v2(float* p, float a, float b) {
    asm volatile("red.global.add.v2.f32 [%0], {%1, %2};"
                 :: "l"(p), "f"(a), "f"(b) : "memory");
}

// ---------------------------------------------------------------------------
__global__ void zero_mi_kernel() {
    int i = blockIdx.x * blockDim.x + threadIdx.x;
    if (i < N_NODES * D / 4)
        reinterpret_cast<float4*>(g_mi)[i] = make_float4(0.f, 0.f, 0.f, 0.f);
}

// ---------------------------------------------------------------------------
__global__ void prep_bimg_kernel(
    const float* __restrict__ We1, const float* __restrict__ We2,
    const float* __restrict__ Wc1, const float* __restrict__ Wn1,
    const float* __restrict__ Wn2, const float* __restrict__ Wv1)
{
    int idx = blockIdx.x * 256 + threadIdx.x;
    if (idx >= 64 * 16 * 32) return;
    int lane = idx & 31;
    int nt = (idx >> 5) & 15;
    int s = idx >> 9;
    int col = nt * 8 + (lane >> 2);
    int kloc = 2 * (lane & 3);
    const float* W; int kr;
    if (s < 8)       { W = We1; kr = s * 16 + kloc; }
    else if (s < 16) { W = We1; kr = 128 + (s - 8) * 16 + kloc; }
    else if (s < 24) { W = We2; kr = (s - 16) * 16 + kloc; }
    else if (s < 32) { W = Wc1; kr = (s - 24) * 16 + kloc; }
    else if (s < 40) { W = Wn1; kr = (s - 32) * 16 + kloc; }
    else if (s < 48) { W = Wn1; kr = 128 + (s - 40) * 16 + kloc; }
    else if (s < 56) { W = Wn2; kr = (s - 48) * 16 + kloc; }
    else             { W = Wv1; kr = (s - 56) * 16 + kloc; }
    float f00 = W[kr * D + col];
    float f01 = W[(kr + 1) * D + col];
    float f10 = W[(kr + 8) * D + col];
    float f11 = W[(kr + 9) * D + col];
    __nv_bfloat162 h0, l0, h1, l1;
    split_pair(f00, f01, h0, l0);
    split_pair(f10, f11, h1, l1);
    uint4 v;
    v.x = bf2_as_u32(h0); v.y = bf2_as_u32(h1);
    v.z = bf2_as_u32(l0); v.w = bf2_as_u32(l1);
    g_bimg[idx] = v;
}

// ---------------------------------------------------------------------------
// 128-row software-pipelined warp-tile GEMM (3-pass hi/lo bf16) — pab
__device__ __forceinline__ void gemm_tile(
    float (&c)[4][4][4], uint32_t aHi_addr, int base,
    int cg, int rg, int lane)
{
    int lrow = lane & 15;
    int lcol = (lane >> 4) * 8;
    const uint4* bp = g_bimg + (base * 16 + cg * 4) * 32 + lane;
    uint4 b[4], bn[4];
    #pragma unroll
    for (int nt = 0; nt < 4; nt++) b[nt] = __ldg(bp + nt * 32);
    uint32_t abase = aHi_addr + (uint32_t)(((rg * 64 + lrow) * PITCHA + lcol) * 2);
    uint32_t ah[2][4], al[2][4];
    ldsm_x4(ah[0][0], ah[0][1], ah[0][2], ah[0][3], abase);
    ldsm_x4(al[0][0], al[0][1], al[0][2], al[0][3], abase + PLANE * 2);
    #pragma unroll
    for (int kt = 0; kt < 8; kt++) {
        if (kt < 7) {
            #pragma unroll
            for (int nt = 0; nt < 4; nt++) bn[nt] = __ldg(bp + 16 * 32 + nt * 32);
        }
        #pragma unroll
        for (int mt = 0; mt < 4; mt++) {
            int cur = mt & 1, nxt = 1 - cur;
            if (mt < 3) {
                uint32_t addr = abase + (uint32_t)((((mt + 1) * 16) * PITCHA + kt * 16) * 2);
                ldsm_x4(ah[nxt][0], ah[nxt][1], ah[nxt][2], ah[nxt][3], addr);
                ldsm_x4(al[nxt][0], al[nxt][1], al[nxt][2], al[nxt][3], addr + PLANE * 2);
            } else if (kt < 7) {
                uint32_t addr = abase + (uint32_t)(((kt + 1) * 16) * 2);
                ldsm_x4(ah[nxt][0], ah[nxt][1], ah[nxt][2], ah[nxt][3], addr);
                ldsm_x4(al[nxt][0], al[nxt][1], al[nxt][2], al[nxt][3], addr + PLANE * 2);
            }
            #pragma unroll
            for (int nt = 0; nt < 4; nt++) {
                mma_bf16(c[mt][nt], ah[cur][0], ah[cur][1], ah[cur][2], ah[cur][3], b[nt].x, b[nt].y);
                mma_bf16(c[mt][nt], ah[cur][0], ah[cur][1], ah[cur][2], ah[cur][3], b[nt].z, b[nt].w);
                mma_bf16(c[mt][nt], al[cur][0], al[cur][1], al[cur][2], al[cur][3], b[nt].x, b[nt].y);
            }
        }
        #pragma unroll
        for (int nt = 0; nt < 4; nt++) b[nt] = bn[nt];
        bp += 16 * 32;
    }
}

// 64-row warp-tile GEMM (32 accumulators) — edge + node_post, 3 blocks/SM
__device__ __forceinline__ void gemm_tile64(
    float (&c)[2][4][4], uint32_t aHi_addr, int base,
    int cg, int rg, int lane)
{
    int lrow = lane & 15;
    int lcol = (lane >> 4) * 8;
    const uint4* bp = g_bimg + (base * 16 + cg * 4) * 32 + lane;
    uint32_t abase = aHi_addr + (uint32_t)(((rg * 32 + lrow) * PITCHA + lcol) * 2);
    #pragma unroll
    for (int kt = 0; kt < 8; kt++) {
        uint4 b[4];
        #pragma unroll
        for (int nt = 0; nt < 4; nt++) b[nt] = __ldg(bp + nt * 32);
        #pragma unroll
        for (int mt = 0; mt < 2; mt++) {
            uint32_t addr = abase + (uint32_t)(((mt * 16) * PITCHA + kt * 16) * 2);
            uint32_t ah0, ah1, ah2, ah3, al0, al1, al2, al3;
            ldsm_x4(ah0, ah1, ah2, ah3, addr);
            ldsm_x4(al0, al1, al2, al3, addr + PLANE64 * 2);
            #pragma unroll
            for (int nt = 0; nt < 4; nt++) {
                mma_bf16(c[mt][nt], ah0, ah1, ah2, ah3, b[nt].x, b[nt].y);
                mma_bf16(c[mt][nt], ah0, ah1, ah2, ah3, b[nt].z, b[nt].w);
                mma_bf16(c[mt][nt], al0, al1, al2, al3, b[nt].x, b[nt].y);
            }
        }
        bp += 16 * 32;
    }
}

#define BIG_SMEM  75776   // pab (128-row planes)
#define EDGE_SMEM 37632   // edge / node_post (64-row planes)

// ---------------------------------------------------------------------------
// pab_kernel (verified R11-R15): P_A, P_B, vel weights + coord base
__global__ __launch_bounds__(256, 2) void pab_kernel(
    const float* __restrict__ h, const float* __restrict__ be1,
    const float* __restrict__ coord, const float* __restrict__ vel,
    const float* __restrict__ bv1, const float* __restrict__ Wv2,
    const float* __restrict__ bv2,
    float* __restrict__ coord_out)
{
    extern __shared__ __align__(16) char smem[];
    __nv_bfloat16* aHi = (__nv_bfloat16*)smem;
    __nv_bfloat16* aLo = aHi + PLANE;
    float* s_be1 = (float*)(smem + 69632);
    float* s_bv1 = s_be1 + 128;
    float* s_wv2 = s_bv1 + 128;
    float* s_wp  = (float*)smem;

    int t = threadIdx.x;
    int lane = t & 31, wid = t >> 5;
    int cg = wid & 3, rg = wid >> 2;
    int n0 = blockIdx.x * 128;
    uint32_t aHi_addr = smem_u32(aHi);

    if (t < 128) { s_be1[t] = be1[t]; s_bv1[t] = bv1[t]; s_wv2[t] = Wv2[t]; }

    {
        int r = t >> 1;
        int node = n0 + r; if (node >= N_NODES) node = N_NODES - 1;
        int ch = (t & 1) * 64;
        const float* src = h + node * D + ch;
        __nv_bfloat16* ph = aHi + r * PITCHA + ch;
        __nv_bfloat16* pl = aLo + r * PITCHA + ch;
        #pragma unroll
        for (int j = 0; j < 16; j++) {
            float4 v = *(const float4*)(src + 4 * j);
            __nv_bfloat162 h2a, l2a, h2b, l2b;
            split_pair(v.x, v.y, h2a, l2a);
            split_pair(v.z, v.w, h2b, l2b);
            *(__nv_bfloat162*)(ph + 4 * j)     = h2a;
            *(__nv_bfloat162*)(ph + 4 * j + 2) = h2b;
            *(__nv_bfloat162*)(pl + 4 * j)     = l2a;
            *(__nv_bfloat162*)(pl + 4 * j + 2) = l2b;
        }
    }
    __syncthreads();

    float c[4][4][4];
    #pragma unroll
    for (int mt = 0; mt < 4; mt++)
        #pragma unroll
        for (int nt = 0; nt < 4; nt++)
            #pragma unroll
            for (int j = 0; j < 4; j++) c[mt][nt][j] = 0.f;

    int q = lane >> 2;
    int kq = 2 * (lane & 3);

    gemm_tile(c, aHi_addr, 0, cg, rg, lane);
    #pragma unroll
    for (int mt = 0; mt < 4; mt++) {
        int row0 = rg * 64 + mt * 16 + q;
        int row1 = row0 + 8;
        bool v0 = (n0 + row0) < N_NODES, v1 = (n0 + row1) < N_NODES;
        #pragma unroll
        for (int nt = 0; nt < 4; nt++) {
            int col = cg * 32 + nt * 8 + kq;
            float b0 = s_be1[col], b1 = s_be1[col + 1];
            if (v0) *(float2*)&g_pa[(n0 + row0) * D + col] =
                make_float2(c[mt][nt][0] + b0, c[mt][nt][1] + b1);
            if (v1) *(float2*)&g_pa[(n0 + row1) * D + col] =
                make_float2(c[mt][nt][2] + b0, c[mt][nt][3] + b1);
            c[mt][nt][0] = c[mt][nt][1] = c[mt][nt][2] = c[mt][nt][3] = 0.f;
        }
    }
    gemm_tile(c, aHi_addr, 8, cg, rg, lane);
    #pragma unroll
    for (int mt = 0; mt < 4; mt++) {
        int row0 = rg * 64 + mt * 16 + q;
        int row1 = row0 + 8;
        bool v0 = (n0 + row0) < N_NODES, v1 = (n0 + row1) < N_NODES;
        #pragma unroll
        for (int nt = 0; nt < 4; nt++) {
            int col = cg * 32 + nt * 8 + kq;
            if (v0) *(float2*)&g_pb[(n0 + row0) * D + col] =
                make_float2(c[mt][nt][0], c[mt][nt][1]);
            if (v1) *(float2*)&g_pb[(n0 + row1) * D + col] =
                make_float2(c[mt][nt][2], c[mt][nt][3]);
            c[mt][nt][0] = c[mt][nt][1] = c[mt][nt][2] = c[mt][nt][3] = 0.f;
        }
    }
    gemm_tile(c, aHi_addr, 56, cg, rg, lane);
    __syncthreads();
    #pragma unroll
    for (int mt = 0; mt < 4; mt++) {
        float p0 = 0.f, p1 = 0.f;
        #pragma unroll
        for (int nt = 0; nt < 4; nt++) {
            int col = cg * 32 + nt * 8 + kq;
            float b0 = s_bv1[col], b1 = s_bv1[col + 1];
            float w0 = s_wv2[col], w1 = s_wv2[col + 1];
            p0 = fmaf(silu(c[mt][nt][0] + b0), w0, p0);
            p0 = fmaf(silu(c[mt][nt][1] + b1), w1, p0);
            p1 = fmaf(silu(c[mt][nt][2] + b0), w0, p1);
            p1 = fmaf(silu(c[mt][nt][3] + b1), w1, p1);
        }
        p0 += __shfl_xor_sync(0xffffffffu, p0, 1);
        p0 += __shfl_xor_sync(0xffffffffu, p0, 2);
        p1 += __shfl_xor_sync(0xffffffffu, p1, 1);
        p1 += __shfl_xor_sync(0xffffffffu, p1, 2);
        if ((lane & 3) == 0) {
            int row0 = rg * 64 + mt * 16 + q;
            s_wp[row0 * 4 + cg]       = p0;
            s_wp[(row0 + 8) * 4 + cg] = p1;
        }
    }
    __syncthreads();
    if (t < 128 && (n0 + t) < N_NODES) {
        float vw = s_wp[t * 4] + s_wp[t * 4 + 1] + s_wp[t * 4 + 2] + s_wp[t * 4 + 3] + bv2[0];
        int n = n0 + t;
        #pragma unroll
        for (int i = 0; i < 3; i++)
            coord_out[n * 3 + i] = coord[n * 3 + i] + vel[n * 3 + i] * vw;
    }
}

// ---------------------------------------------------------------------------
// edge kernel: 64 edges/block, 3 blocks/SM, warp-per-row coalesced gather
__global__ __launch_bounds__(256, 3) void edge_kernel(
    const float* __restrict__ coord,
    const int* __restrict__ ei,
    const float* __restrict__ be2,
    const float* __restrict__ bc1,
    const float* __restrict__ Wc2, const float* __restrict__ bc2,
    const float* __restrict__ We1,
    float* __restrict__ coord_out)
{
    extern __shared__ __align__(16) char smem[];
    __nv_bfloat16* aHi = (__nv_bfloat16*)smem;              // 17408 B
    __nv_bfloat16* aLo = aHi + PLANE64;                     // 17408 B
    float* s_be2  = (float*)(smem + 34816);
    float* s_bc1  = s_be2 + 128;
    float* s_wc2  = s_bc1 + 128;
    int*   s_r    = (int*)(smem + 36352);    // 64 ints
    float* s_diff = (float*)(smem + 36608);  // 64*3 floats
    float* s_wp   = (float*)smem;            // L3 partials alias plane

    int t = threadIdx.x;
    int lane = t & 31, wid = t >> 5;
    int cg = wid & 3, rg = wid >> 2;        // rg in {0,1}
    int e0 = blockIdx.x * 64;

    uint32_t aHi_addr = smem_u32(aHi);

    if (t < 128) { s_be2[t] = be2[t]; s_bc1[t] = bc1[t]; s_wc2[t] = Wc2[t]; }

    // ---- warp-per-row gather + act1: each warp processes 8 edges;
    //      32 lanes cover a full 128-col row (fully coalesced 512B LDGs) ----
    {
        float4 w = *(const float4*)(We1 + 256 * D + 4 * lane);  // hoisted, warp-wide row
        int rowbase = wid * 8;
        #pragma unroll
        for (int e = 0; e < 8; e++) {
            int row = rowbase + e;
            int eidx = e0 + row;
            int cl = (eidx < N_EDGES) ? eidx : (N_EDGES - 1);
            int r = ei[cl], cc = ei[N_EDGES + cl];     // warp-uniform broadcast
            float dx = coord[r * 3 + 0] - coord[cc * 3 + 0];
            float dy = coord[r * 3 + 1] - coord[cc * 3 + 1];
            float dz = coord[r * 3 + 2] - coord[cc * 3 + 2];
            float rad = dx * dx + dy * dy + dz * dz;
            if (lane == 0) {
                float inv = 1.0f / (sqrtf(rad) + 1e-8f);
                s_r[row] = r;
                s_diff[row * 3 + 0] = dx * inv;
                s_diff[row * 3 + 1] = dy * inv;
                s_diff[row * 3 + 2] = dz * inv;
            }
            float4 a = *(const float4*)(g_pa + (size_t)r * D + 4 * lane);
            float4 b = *(const float4*)(g_pb + (size_t)cc * D + 4 * lane);
            float u0 = silu(a.x + b.x + rad * w.x);
            float u1 = silu(a.y + b.y + rad * w.y);
            float u2 = silu(a.z + b.z + rad * w.z);
            float u3 = silu(a.w + b.w + rad * w.w);
            __nv_bfloat162 h2a, l2a, h2b, l2b;
            split_pair(u0, u1, h2a, l2a);
            split_pair(u2, u3, h2b, l2b);
            uint2 HV, LV;
            HV.x = bf2_as_u32(h2a); HV.y = bf2_as_u32(h2b);
            LV.x = bf2_as_u32(l2a); LV.y = bf2_as_u32(l2b);
            *(uint2*)(aHi + row * PITCHA + 4 * lane) = HV;
            *(uint2*)(aLo + row * PITCHA + 4 * lane) = LV;
        }
    }
    __syncthreads();

    float c[2][4][4];
    #pragma unroll
    for (int mt = 0; mt < 2; mt++)
        #pragma unroll
        for (int nt = 0; nt < 4; nt++)
            #pragma unroll
            for (int j = 0; j < 4; j++) c[mt][nt][j] = 0.f;

    int q = lane >> 2;
    int kq = 2 * (lane & 3);

    // ============ LAYER 2: act1 @ We2 -> m_ij ============
    gemm_tile64(c, aHi_addr, 16, cg, rg, lane);
    __syncthreads();
    #pragma unroll
    for (int mt = 0; mt < 2; mt++) {
        int row0 = rg * 32 + mt * 16 + q;
        int row1 = row0 + 8;
        bool v0 = (e0 + row0) < N_EDGES, v1 = (e0 + row1) < N_EDGES;
        int n0 = s_r[row0], n1 = s_r[row1];
        #pragma unroll
        for (int nt = 0; nt < 4; nt++) {
            int col = cg * 32 + nt * 8 + kq;
            float b0 = s_be2[col], b1 = s_be2[col + 1];
            float v00 = silu(c[mt][nt][0] + b0);
            float v01 = silu(c[mt][nt][1] + b1);
            float v10 = silu(c[mt][nt][2] + b0);
            float v11 = silu(c[mt][nt][3] + b1);
            __nv_bfloat162 h2, l2;
            split_pair(v00, v01, h2, l2);
            *(__nv_bfloat162*)(aHi + row0 * PITCHA + col) = h2;
            *(__nv_bfloat162*)(aLo + row0 * PITCHA + col) = l2;
            split_pair(v10, v11, h2, l2);
            *(__nv_bfloat162*)(aHi + row1 * PITCHA + col) = h2;
            *(__nv_bfloat162*)(aLo + row1 * PITCHA + col) = l2;
            if (v0) red_add_v2(&g_mi[n0 * D + col], v00, v01);
            if (v1) red_add_v2(&g_mi[n1 * D + col], v10, v11);
            c[mt][nt][0] = c[mt][nt][1] = c[mt][nt][2] = c[mt][nt][3] = 0.f;
        }
    }
    __syncthreads();

    // ============ LAYER 3: m_ij @ Wc1 -> per-edge weight ============
    gemm_tile64(c, aHi_addr, 24, cg, rg, lane);
    __syncthreads();
    #pragma unroll
    for (int mt = 0; mt < 2; mt++) {
        float p0 = 0.f, p1 = 0.f;
        #pragma unroll
        for (int nt = 0; nt < 4; nt++) {
            int col = cg * 32 + nt * 8 + kq;
            float b0 = s_bc1[col], b1 = s_bc1[col + 1];
            float w0 = s_wc2[col], w1 = s_wc2[col + 1];
            p0 = fmaf(silu(c[mt][nt][0] + b0), w0, p0);
            p0 = fmaf(silu(c[mt][nt][1] + b1), w1, p0);
            p1 = fmaf(silu(c[mt][nt][2] + b0), w0, p1);
            p1 = fmaf(silu(c[mt][nt][3] + b1), w1, p1);
        }
        p0 += __shfl_xor_sync(0xffffffffu, p0, 1);
        p0 += __shfl_xor_sync(0xffffffffu, p0, 2);
        p1 += __shfl_xor_sync(0xffffffffu, p1, 1);
        p1 += __shfl_xor_sync(0xffffffffu, p1, 2);
        if ((lane & 3) == 0) {
            int row0 = rg * 32 + mt * 16 + q;
            s_wp[row0 * 4 + cg]       = p0;
            s_wp[(row0 + 8) * 4 + cg] = p1;
        }
    }
    __syncthreads();

    if (t < 64 && (e0 + t) < N_EDGES) {
        float w = s_wp[t * 4] + s_wp[t * 4 + 1] + s_wp[t * 4 + 2] + s_wp[t * 4 + 3] + bc2[0];
        int rr = s_r[t];
        atomicAdd(&coord_out[rr * 3 + 0], s_diff[t * 3 + 0] * w);
        atomicAdd(&coord_out[rr * 3 + 1], s_diff[t * 3 + 1] * w);
        atomicAdd(&coord_out[rr * 3 + 2], s_diff[t * 3 + 2] * w);
    }
}

// ---------------------------------------------------------------------------
// node_post: 64 nodes/block, 3 blocks/SM (verified R15)
__global__ __launch_bounds__(256, 3) void node_post_kernel(
    const float* __restrict__ h,
    const float* __restrict__ bn1, const float* __restrict__ bn2,
    float* __restrict__ h_out)
{
    extern __shared__ __align__(16) char smem[];
    __nv_bfloat16* aHi = (__nv_bfloat16*)smem;              // 17408 B
    __nv_bfloat16* aLo = aHi + PLANE64;                     // 17408 B
    float* s_bn1 = (float*)(smem + 34816);
    float* s_bn2 = s_bn1 + 128;

    int t = threadIdx.x;
    int lane = t & 31, wid = t >> 5;
    int cg = wid & 3, rg = wid >> 2;        // rg in {0,1}
    int n0 = blockIdx.x * 64;
    uint32_t aHi_addr = smem_u32(aHi);

    if (t < 128) { s_bn1[t] = bn1[t]; s_bn2[t] = bn2[t]; }

    float c[2][4][4];
    #pragma unroll
    for (int mt = 0; mt < 2; mt++)
        #pragma unroll
        for (int nt = 0; nt < 4; nt++)
            #pragma unroll
            for (int j = 0; j < 4; j++) c[mt][nt][j] = 0.f;

    int q = lane >> 2;
    int kq = 2 * (lane & 3);

    auto stage_rows = [&](const float* base) {
        int row = t >> 2;
        int node = n0 + row; if (node >= N_NODES) node = N_NODES - 1;
        int ch = (t & 3) * 32;
        const float* src = base + node * D + ch;
        __nv_bfloat16* ph = aHi + row * PITCHA + ch;
        __nv_bfloat16* pl = aLo + row * PITCHA + ch;
        #pragma unroll
        for (int j = 0; j < 8; j++) {
            float4 v = *(const float4*)(src + 4 * j);
            __nv_bfloat162 h2a, l2a, h2b, l2b;
            split_pair(v.x, v.y, h2a, l2a);
            split_pair(v.z, v.w, h2b, l2b);
            *(__nv_bfloat162*)(ph + 4 * j)     = h2a;
            *(__nv_bfloat162*)(ph + 4 * j + 2) = h2b;
            *(__nv_bfloat162*)(pl + 4 * j)     = l2a;
            *(__nv_bfloat162*)(pl + 4 * j + 2) = l2b;
        }
    };

    // layer 1: [h | m_i] @ Wn1 (K=256 via two staged tiles)
    stage_rows(h);
    __syncthreads();
    gemm_tile64(c, aHi_addr, 32, cg, rg, lane);
    __syncthreads();
    stage_rows(g_mi);
    __syncthreads();
    gemm_tile64(c, aHi_addr, 40, cg, rg, lane);
    __syncthreads();

    // epilogue: silu(C + bn1) -> planes
    #pragma unroll
    for (int mt = 0; mt < 2; mt++) {
        int row0 = rg * 32 + mt * 16 + q;
        int row1 = row0 + 8;
        #pragma unroll
        for (int nt = 0; nt < 4; nt++) {
            int col = cg * 32 + nt * 8 + kq;
            float b0 = s_bn1[col], b1 = s_bn1[col + 1];
            float v00 = silu(c[mt][nt][0] + b0);
            float v01 = silu(c[mt][nt][1] + b1);
            float v10 = silu(c[mt][nt][2] + b0);
            float v11 = silu(c[mt][nt][3] + b1);
            __nv_bfloat162 h2, l2;
            split_pair(v00, v01, h2, l2);
            *(__nv_bfloat162*)(aHi + row0 * PITCHA + col) = h2;
            *(__nv_bfloat162*)(aLo + row0 * PITCHA + col) = l2;
            split_pair(v10, v11, h2, l2);
            *(__nv_bfloat162*)(aHi + row1 * PITCHA + col) = h2;
            *(__nv_bfloat162*)(aLo + row1 * PITCHA + col) = l2;
            c[mt][nt][0] = c[mt][nt][1] = c[mt][nt][2] = c[mt][nt][3] = 0.f;
        }
    }
    __syncthreads();

    // layer 2: act @ Wn2, write h_out
    gemm_tile64(c, aHi_addr, 48, cg, rg, lane);

    #pragma unroll
    for (int mt = 0; mt < 2; mt++) {
        int row0 = rg * 32 + mt * 16 + q;
        int row1 = row0 + 8;
        bool v0 = (n0 + row0) < N_NODES, v1 = (n0 + row1) < N_NODES;
        #pragma unroll
        for (int nt = 0; nt < 4; nt++) {
            int col = cg * 32 + nt * 8 + kq;
            float b0 = s_bn2[col], b1 = s_bn2[col + 1];
            if (v0) {
                float2 o = make_float2(c[mt][nt][0] + b0, c[mt][nt][1] + b1);
                *(float2*)&h_out[(n0 + row0) * D + col] = o;
            }
            if (v1) {
                float2 o = make_float2(c[mt][nt][2] + b0, c[mt][nt][3] + b1);
                *(float2*)&h_out[(n0 + row1) * D + col] = o;
            }
        }
    }
}

// ---------------------------------------------------------------------------
extern "C" void kernel_launch(void* const* d_in, const int* in_sizes, int n_in,
                              void* d_out, int out_size)
{
    const float* h     = (const float*)d_in[0];
    const float* coord = (const float*)d_in[1];
    const float* vel   = (const float*)d_in[2];
    const int*   ei    = (const int*)  d_in[3];
    const float* We1 = (const float*)d_in[4];  const float* be1 = (const float*)d_in[5];
    const float* We2 = (const float*)d_in[6];  const float* be2 = (const float*)d_in[7];
    const float* Wc1 = (const float*)d_in[8];  const float* bc1 = (const float*)d_in[9];
    const float* Wc2 = (const float*)d_in[10]; const float* bc2 = (const float*)d_in[11];
    const float* Wv1 = (const float*)d_in[12]; const float* bv1 = (const float*)d_in[13];
    const float* Wv2 = (const float*)d_in[14]; const float* bv2 = (const float*)d_in[15];
    const float* Wn1 = (const float*)d_in[16]; const float* bn1 = (const float*)d_in[17];
    const float* Wn2 = (const float*)d_in[18]; const float* bn2 = (const float*)d_in[19];

    float* h_out     = (float*)d_out;                  // [N, 128]
    float* coord_out = (float*)d_out + N_NODES * D;    // [N, 3]

    cudaFuncSetAttribute(edge_kernel, cudaFuncAttributeMaxDynamicSharedMemorySize, EDGE_SMEM);
    cudaFuncSetAttribute(node_post_kernel, cudaFuncAttributeMaxDynamicSharedMemorySize, EDGE_SMEM);
    cudaFuncSetAttribute(pab_kernel, cudaFuncAttributeMaxDynamicSharedMemorySize, BIG_SMEM);

    int edge_blocks = (N_EDGES + 63) / 64;
    int npost_blocks = (N_NODES + 63) / 64;
    int nblk128 = (N_NODES + 127) / 128;

    zero_mi_kernel<<<(N_NODES * D / 4 + 255) / 256, 256>>>();
    prep_bimg_kernel<<<(64 * 16 * 32 + 255) / 256, 256>>>(We1, We2, Wc1, Wn1, Wn2, Wv1);
    pab_kernel<<<nblk128, 256, BIG_SMEM>>>(h, be1, coord, vel, bv1, Wv2, bv2, coord_out);
    edge_kernel<<<edge_blocks, 256, EDGE_SMEM>>>(coord, ei,
                                                 be2, bc1, Wc2, bc2, We1, coord_out);
    node_post_kernel<<<npost_blocks, 256, EDGE_SMEM>>>(h, bn1, bn2, h_out);
}